// round 1
// baseline (speedup 1.0000x reference)
#include <cuda_runtime.h>
#include <cuda_bf16.h>

// Problem constants
#define B_   128
#define F_   1024
#define W_   32
#define H_   64
#define G4   256     // 4*H
// x layout: [B, F, W]  -> x[b*F_*W_ + f*W_ + t]
// G layout: [B, W, 4H] -> g_G[(b*W_ + t)*G4 + n],  GEMM row m = b*W_ + t

// Scratch: gate pre-activations from the input path (loop-invariant)
__device__ float g_G[B_ * W_ * G4];   // 4 MB

// ---------------------------------------------------------------------------
// Kernel 1: G[m, n] = sum_k x[b, k, t] * Wx[k, n] + b_lstm[n],  m = b*32 + t
// M = 4096, K = 1024, N = 256.  BM=128, BN=64, BK=16, 128 threads, 8x8 micro.
// Grid (32, 4) = 128 CTAs = one wave.
// ---------------------------------------------------------------------------
__global__ __launch_bounds__(128)
void gate_gemm(const float* __restrict__ x,
               const float* __restrict__ Wx,
               const float* __restrict__ bl) {
    __shared__ float As[2][16][128];   // [buf][k][m]
    __shared__ float Bs[2][16][64];    // [buf][k][n]

    const int tid = threadIdx.x;
    const int bm  = blockIdx.x;        // 0..31  (m tile)
    const int bn  = blockIdx.y;        // 0..3   (n tile)
    const int b0  = bm * 4;            // first batch row of this m-tile (BM=128 = 4 b's * 32 t's)
    const int n0  = bn * 64;

    // A loader mapping: 128 threads cover 128x16 floats as 4x float4 each.
    const int aj = tid & 7;            // t-quad: t = 4*aj .. 4*aj+3
    const int as = tid >> 3;           // kk within tile: 0..15
    // B loader mapping: 2x float4 each.
    const int bn4 = tid & 15;          // n-quad
    const int bkr = tid >> 4;          // 0..7 -> kk = bkr and bkr+8

    // Compute mapping: 16x8 thread grid, 8x8 microtile.
    const int ty = tid >> 3;           // 0..15  (rows ty*8..+7)
    const int tx = tid & 7;            // 0..7   (cols tx*8..+7)

    const float* xA = x  + (size_t)b0 * (F_ * W_) + as * W_ + aj * 4;
    const float* wB = Wx + bkr * G4 + n0 + bn4 * 4;

    float4 aR[4];
    float4 bR[2];
    float  acc[8][8];
#pragma unroll
    for (int i = 0; i < 8; i++)
#pragma unroll
        for (int j = 0; j < 8; j++) acc[i][j] = 0.f;

    // Prefetch k-tile 0 into registers
#pragma unroll
    for (int bb = 0; bb < 4; bb++)
        aR[bb] = *reinterpret_cast<const float4*>(xA + (size_t)bb * (F_ * W_));
    bR[0] = *reinterpret_cast<const float4*>(wB);
    bR[1] = *reinterpret_cast<const float4*>(wB + 8 * G4);

    int buf = 0;
    for (int kt = 0; kt < 64; kt++) {
        // Stage current tile into smem
#pragma unroll
        for (int bb = 0; bb < 4; bb++)
            *reinterpret_cast<float4*>(&As[buf][as][bb * 32 + aj * 4]) = aR[bb];
        *reinterpret_cast<float4*>(&Bs[buf][bkr][bn4 * 4])     = bR[0];
        *reinterpret_cast<float4*>(&Bs[buf][bkr + 8][bn4 * 4]) = bR[1];
        __syncthreads();

        // Prefetch next tile (global latency hidden under compute)
        if (kt < 63) {
            const float* xN = xA + (size_t)(kt + 1) * 16 * W_;
            const float* wN = wB + (size_t)(kt + 1) * 16 * G4;
#pragma unroll
            for (int bb = 0; bb < 4; bb++)
                aR[bb] = *reinterpret_cast<const float4*>(xN + (size_t)bb * (F_ * W_));
            bR[0] = *reinterpret_cast<const float4*>(wN);
            bR[1] = *reinterpret_cast<const float4*>(wN + 8 * G4);
        }

        // Compute 16 k-steps
#pragma unroll
        for (int kk = 0; kk < 16; kk++) {
            float4 a0 = *reinterpret_cast<const float4*>(&As[buf][kk][ty * 8]);
            float4 a1 = *reinterpret_cast<const float4*>(&As[buf][kk][ty * 8 + 4]);
            float4 c0 = *reinterpret_cast<const float4*>(&Bs[buf][kk][tx * 8]);
            float4 c1 = *reinterpret_cast<const float4*>(&Bs[buf][kk][tx * 8 + 4]);
            float av[8] = {a0.x, a0.y, a0.z, a0.w, a1.x, a1.y, a1.z, a1.w};
            float bv[8] = {c0.x, c0.y, c0.z, c0.w, c1.x, c1.y, c1.z, c1.w};
#pragma unroll
            for (int i = 0; i < 8; i++)
#pragma unroll
                for (int j = 0; j < 8; j++)
                    acc[i][j] = fmaf(av[i], bv[j], acc[i][j]);
        }
        buf ^= 1;
        __syncthreads();
    }

    // Epilogue: add bias, store to g_G
    float bias[8];
#pragma unroll
    for (int j = 0; j < 8; j++) bias[j] = bl[n0 + tx * 8 + j];

    const int m0 = bm * 128;
#pragma unroll
    for (int i = 0; i < 8; i++) {
        int m = m0 + ty * 8 + i;
        float4 o0, o1;
        o0.x = acc[i][0] + bias[0];
        o0.y = acc[i][1] + bias[1];
        o0.z = acc[i][2] + bias[2];
        o0.w = acc[i][3] + bias[3];
        o1.x = acc[i][4] + bias[4];
        o1.y = acc[i][5] + bias[5];
        o1.z = acc[i][6] + bias[6];
        o1.w = acc[i][7] + bias[7];
        *reinterpret_cast<float4*>(&g_G[(size_t)m * G4 + n0 + tx * 8])     = o0;
        *reinterpret_cast<float4*>(&g_G[(size_t)m * G4 + n0 + tx * 8 + 4]) = o1;
    }
}

// ---------------------------------------------------------------------------
// Kernel 2: per-batch LSTM recurrence. One CTA per batch element (128 CTAs),
// 256 threads = one per gate column. Wh column cached in registers.
// out[b, t, j] = c after step t (reference appends the CELL state).
// ---------------------------------------------------------------------------
__device__ __forceinline__ float sigmoidf_(float v) {
    return 1.0f / (1.0f + __expf(-v));
}

__global__ __launch_bounds__(256)
void lstm_rec(const float* __restrict__ Wh, float* __restrict__ out) {
    const int b = blockIdx.x;
    const int g = threadIdx.x;     // 0..255 gate column

    __shared__ float h_s[H_];
    __shared__ float gs[G4];

    // Cache Wh[:, g] in registers (64 values). Coalesced: warp reads 128B rows.
    float wh[H_];
#pragma unroll
    for (int k = 0; k < H_; k++) wh[k] = Wh[k * G4 + g];

    if (g < H_) h_s[g] = 0.0f;
    float c = 0.0f;                // live in threads g < 64

    const float* Gb = g_G + (size_t)b * W_ * G4;
    float gv = Gb[g];              // prefetch t = 0
    __syncthreads();

    for (int t = 0; t < W_; t++) {
        float acc = gv;
        if (t < W_ - 1) gv = Gb[(t + 1) * G4 + g];   // prefetch next step

        // acc += h . Wh[:, g]   (h broadcast from smem, weights in regs)
#pragma unroll
        for (int k = 0; k < H_; k++) acc = fmaf(h_s[k], wh[k], acc);

        gs[g] = acc;
        __syncthreads();

        if (g < H_) {
            float ig = sigmoidf_(gs[g]);
            float fg = sigmoidf_(gs[H_ + g]);
            float gg = tanhf(gs[2 * H_ + g]);
            float og = sigmoidf_(gs[3 * H_ + g]);
            c = fg * c + ig * gg;
            float hn = og * tanhf(c);
            out[(size_t)b * (W_ * H_) + t * H_ + g] = c;   // output = cell state
            h_s[g] = hn;
        }
        __syncthreads();
    }
}

// ---------------------------------------------------------------------------
// Launch
// ---------------------------------------------------------------------------
extern "C" void kernel_launch(void* const* d_in, const int* in_sizes, int n_in,
                              void* d_out, int out_size) {
    const float* x    = (const float*)d_in[0];   // [B, F, W]
    // d_in[1..5] = W_state, b_state, W_in, w_attn, b_attn: mathematically dead
    // (softmax over a size-1 axis is identically 1.0, so x_tilde == x_t).
    const float* Wx   = (const float*)d_in[6];   // [F, 4H]
    const float* Wh   = (const float*)d_in[7];   // [H, 4H]
    const float* blm  = (const float*)d_in[8];   // [4H]
    float* out = (float*)d_out;                  // [B, W, H]

    dim3 gg(32, 4);
    gate_gemm<<<gg, 128>>>(x, Wx, blm);
    lstm_rec<<<B_, 256>>>(Wh, out);
}